// round 14
// baseline (speedup 1.0000x reference)
#include <cuda_runtime.h>
#include <cstdint>
#include <cstddef>

// Problem dims
#define TT 700
#define BB 64
#define UU 400
#define GG 1600   // 4*U
#define FF 3
#define NSTEPS 702    // wavefront: L0@s, L1@s-1, L2@s-2
#define NCTA_W 145    // 29 L0 (14u) + 58 L1 (7u) + 58 L2 (7u); max 22400 col·k

typedef unsigned long long ull;

// ---------------- static device scratch -------------------------------------
__device__ float g_xaux[(size_t)TT * 3 * BB];   // transposed input [t][d][b]
__device__ float g_h0[(size_t)TT * UU * BB];    // [t][u][b]
__device__ float g_h1[(size_t)TT * UU * BB];
__device__ float g_h2[(size_t)TT * UU * BB];
__device__ unsigned g_flags[NCTA_W];            // zero-init, monotonic barrier counters

// ---------------- helpers ----------------------------------------------------
__device__ __forceinline__ unsigned ld_acq(const unsigned* p) {
    unsigned v;
    asm volatile("ld.acquire.gpu.u32 %0, [%1];" : "=r"(v) : "l"(p) : "memory");
    return v;
}
__device__ __forceinline__ void st_rel(unsigned* p, unsigned v) {
    asm volatile("st.release.gpu.u32 [%0], %1;" :: "l"(p), "r"(v) : "memory");
}
__device__ __forceinline__ void ffma2(ull& d, ull a, ull b) {
    asm("fma.rn.f32x2 %0, %1, %2, %0;" : "+l"(d) : "l"(a), "l"(b));
}
__device__ __forceinline__ ull add2(ull a, ull b) {
    ull r; asm("add.rn.f32x2 %0, %1, %2;" : "=l"(r) : "l"(a), "l"(b)); return r;
}
__device__ __forceinline__ ull dup2(float w) {
    ull r; asm("mov.b64 %0, {%1, %1};" : "=l"(r) : "f"(w)); return r;
}
__device__ __forceinline__ ull pack2(float lo, float hi) {
    ull r; asm("mov.b64 %0, {%1, %2};" : "=l"(r) : "f"(lo), "f"(hi)); return r;
}
__device__ __forceinline__ float f2lo(ull v){ return __int_as_float((int)(unsigned)v); }
__device__ __forceinline__ float f2hi(ull v){ return __int_as_float((int)(v >> 32)); }
__device__ __forceinline__ float sigm(float x) { return 1.0f / (1.0f + __expf(-x)); }
__device__ __forceinline__ float tanh_fast(float x) {
    return 1.0f - 2.0f / (__expf(2.0f * x) + 1.0f);
}

// ---------------- input transpose: x[b][t][d] -> g_xaux[t][d][b] -------------
__global__ void xt_kernel(const float* __restrict__ x)
{
    int t = blockIdx.x;
    int tid = threadIdx.x;          // 192 = 64 b * 3 d
    int b = tid / 3, d = tid % 3;
    g_xaux[(size_t)t * (3 * BB) + d * BB + b] = x[(size_t)b * (TT * FF) + t * FF + d];
}

// ---------------- fused 3-layer wavefront (R13 shapes, 145-CTA balance) -------
// 145 CTAs x 256 threads, persistent, 702 steps, one grid barrier per step.
//   cta   0..28 : L0, 14 units (56 cols), k=400(+3 aux). 2 chalf x 4 k-slices.
//   cta  29..86 : L1,  7 units (28 cols), k=800. 8 k-slices(100).
//   cta  87..144: L2,  7 units (28 cols), k=800. 8 k-slices(100).
// cg-group = 7 REAL cols + 1 pad slot (pad loaded via float4, never FMA'd).
// w rows padded: L0 = 256 B/row ([chalf][cg][8f]), L1/2 = 128 B/row ([cg][8f]).
// Thread = 7 cols x 4 batch-pairs x 100 k = 2800 FFMA2/step (was 3200).
// Tail CTAs (units >= 400) zero-padded weights + guarded gates/stores.
// smem: w 102400 + red 57344 + waux 768 = 160512 B.
#define WSM_BYTES 102400
#define RED_BYTES 57344
#define WAVE_SMEM (WSM_BYTES + RED_BYTES + 768)

template<int RB>   // w row stride in bytes: 256 (L0) or 128 (L1/2)
__device__ __forceinline__ void accum100(ull (&acc)[7][4],
                                         const char* __restrict__ wrow0,
                                         const float* __restrict__ hsrc,
                                         int pg)
{
    const char* hp = (const char*)hsrc + pg * 32;   // this thread's 4 pairs
    ulonglong2 hb[2][4][2];                          // [buf][row][half]
#pragma unroll
    for (int j = 0; j < 4; j++) {
        hb[0][j][0] = *(const ulonglong2*)(hp + j * 256);
        hb[0][j][1] = *(const ulonglong2*)(hp + j * 256 + 16);
    }
    const char* wrow = wrow0;
#pragma unroll 2
    for (int rc = 0; rc < 100; rc += 4) {
        int cur = (rc >> 2) & 1;
        if (rc < 96) {
            int nxt = cur ^ 1;
#pragma unroll
            for (int j = 0; j < 4; j++) {
                hb[nxt][j][0] = *(const ulonglong2*)(hp + (rc + 4 + j) * 256);
                hb[nxt][j][1] = *(const ulonglong2*)(hp + (rc + 4 + j) * 256 + 16);
            }
        }
#pragma unroll
        for (int j = 0; j < 4; j++) {
            float4 wa = *(const float4*)(wrow);
            float4 wb = *(const float4*)(wrow + 16);
            ull w0 = dup2(wa.x), w1 = dup2(wa.y), w2 = dup2(wa.z), w3 = dup2(wa.w);
            ull w4 = dup2(wb.x), w5 = dup2(wb.y), w6 = dup2(wb.z);  // wb.w = pad
            ulonglong2 hA = hb[cur][j][0];
            ulonglong2 hB = hb[cur][j][1];
            ffma2(acc[0][0], hA.x, w0); ffma2(acc[0][1], hA.y, w0);
            ffma2(acc[0][2], hB.x, w0); ffma2(acc[0][3], hB.y, w0);
            ffma2(acc[1][0], hA.x, w1); ffma2(acc[1][1], hA.y, w1);
            ffma2(acc[1][2], hB.x, w1); ffma2(acc[1][3], hB.y, w1);
            ffma2(acc[2][0], hA.x, w2); ffma2(acc[2][1], hA.y, w2);
            ffma2(acc[2][2], hB.x, w2); ffma2(acc[2][3], hB.y, w2);
            ffma2(acc[3][0], hA.x, w3); ffma2(acc[3][1], hA.y, w3);
            ffma2(acc[3][2], hB.x, w3); ffma2(acc[3][3], hB.y, w3);
            ffma2(acc[4][0], hA.x, w4); ffma2(acc[4][1], hA.y, w4);
            ffma2(acc[4][2], hB.x, w4); ffma2(acc[4][3], hB.y, w4);
            ffma2(acc[5][0], hA.x, w5); ffma2(acc[5][1], hA.y, w5);
            ffma2(acc[5][2], hB.x, w5); ffma2(acc[5][3], hB.y, w5);
            ffma2(acc[6][0], hA.x, w6); ffma2(acc[6][1], hA.y, w6);
            ffma2(acc[6][2], hB.x, w6); ffma2(acc[6][3], hB.y, w6);
            wrow += RB;
        }
    }
}

// 3 aux rows (input x) — L0 only, same h layout (256 B stride), 7 cols
__device__ __forceinline__ void accum3(ull (&acc)[7][4],
                                       const char* __restrict__ wauxp,
                                       const float* __restrict__ xsrc,
                                       int pg)
{
    const char* hp = (const char*)xsrc + pg * 32;
#pragma unroll
    for (int j = 0; j < 3; j++) {
        ulonglong2 hA = *(const ulonglong2*)(hp + j * 256);
        ulonglong2 hB = *(const ulonglong2*)(hp + j * 256 + 16);
        float4 wa = *(const float4*)(wauxp + j * 256);
        float4 wb = *(const float4*)(wauxp + j * 256 + 16);
        ull w0 = dup2(wa.x), w1 = dup2(wa.y), w2 = dup2(wa.z), w3 = dup2(wa.w);
        ull w4 = dup2(wb.x), w5 = dup2(wb.y), w6 = dup2(wb.z);
        ffma2(acc[0][0], hA.x, w0); ffma2(acc[0][1], hA.y, w0);
        ffma2(acc[0][2], hB.x, w0); ffma2(acc[0][3], hB.y, w0);
        ffma2(acc[1][0], hA.x, w1); ffma2(acc[1][1], hA.y, w1);
        ffma2(acc[1][2], hB.x, w1); ffma2(acc[1][3], hB.y, w1);
        ffma2(acc[2][0], hA.x, w2); ffma2(acc[2][1], hA.y, w2);
        ffma2(acc[2][2], hB.x, w2); ffma2(acc[2][3], hB.y, w2);
        ffma2(acc[3][0], hA.x, w3); ffma2(acc[3][1], hA.y, w3);
        ffma2(acc[3][2], hB.x, w3); ffma2(acc[3][3], hB.y, w3);
        ffma2(acc[4][0], hA.x, w4); ffma2(acc[4][1], hA.y, w4);
        ffma2(acc[4][2], hB.x, w4); ffma2(acc[4][3], hB.y, w4);
        ffma2(acc[5][0], hA.x, w5); ffma2(acc[5][1], hA.y, w5);
        ffma2(acc[5][2], hB.x, w5); ffma2(acc[5][3], hB.y, w5);
        ffma2(acc[6][0], hA.x, w6); ffma2(acc[6][1], hA.y, w6);
        ffma2(acc[6][2], hB.x, w6); ffma2(acc[6][3], hB.y, w6);
    }
}

// LSTM cell, one unit, two batches; z packed f32x2 per gate; c in-place.
__device__ __forceinline__ void cell2(const ull z[4], float& c0, float& c1,
                                      float piv, float pfv, float pov,
                                      float* __restrict__ outp)
{
    float zi0 = f2lo(z[0]), zi1 = f2hi(z[0]);
    float zf0 = f2lo(z[1]), zf1 = f2hi(z[1]);
    float zg0 = f2lo(z[2]), zg1 = f2hi(z[2]);
    float zo0 = f2lo(z[3]), zo1 = f2hi(z[3]);

    float i0 = sigm(zi0 + piv * c0);
    float f0 = sigm(zf0 + pfv * c0);
    float cn0 = f0 * c0 + i0 * tanh_fast(zg0);
    float o0 = sigm(zo0 + pov * cn0);
    float h0 = o0 * tanh_fast(cn0);
    c0 = cn0;

    float i1 = sigm(zi1 + piv * c1);
    float f1 = sigm(zf1 + pfv * c1);
    float cn1 = f1 * c1 + i1 * tanh_fast(zg1);
    float o1 = sigm(zo1 + pov * cn1);
    float h1 = o1 * tanh_fast(cn1);
    c1 = cn1;

    *(ull*)outp = pack2(h0, h1);
}

__global__ void __launch_bounds__(256, 1) wave_kernel(const float* __restrict__ Wx0,
                                                      const float* __restrict__ Wx1,
                                                      const float* __restrict__ Wx2,
                                                      const float* __restrict__ Wh,
                                                      const float* __restrict__ bb,
                                                      const float* __restrict__ pi,
                                                      const float* __restrict__ pf,
                                                      const float* __restrict__ po)
{
    extern __shared__ char smraw[];
    char*  wsm  = smraw;                                  // padded w rows
    ull*   red  = (ull*)(smraw + WSM_BYTES);              // [nslice][ncolsTot][32 pairs]
    char*  waux = smraw + WSM_BYTES + RED_BYTES;          // [3 rows][256 B] L0 x-weights

    const int tid  = threadIdx.x;
    const int cta  = blockIdx.x;
    const int wid  = tid >> 5;
    const int lane = tid & 31;
    const int cg   = lane & 3;     // col-group (7 real cols)
    const int pg   = lane >> 2;    // pair-group (4 pairs)

    int jtype, ubase, nu;
    if (cta < 29)      { jtype = 0; ubase = cta * 14;        nu = 14; }
    else if (cta < 87) { jtype = 1; ubase = (cta - 29) * 7;  nu = 7;  }
    else               { jtype = 2; ubase = (cta - 87) * 7;  nu = 7;  }
    const int ncolsTot = nu * 4;                // 56 or 28 (reduce-buffer cols)
    const int nslice   = (jtype == 0) ? 4 : 8;
    const int rowB     = (jtype == 0) ? 256 : 128;

    const float* Wh0 = Wh;
    const float* Wh1 = Wh + (size_t)UU * GG;
    const float* Wh2 = Wh + (size_t)2 * UU * GG;

    // ---- weight fill into padded layout (25600 float slots, pads zeroed) ----
    for (int idx = tid; idx < 25600; idx += 256) {
        int k, slot;
        if (jtype == 0) { k = idx >> 6; slot = idx & 63; }   // 64 slots/row
        else            { k = idx >> 5; slot = idx & 31; }   // 32 slots/row
        int scg = (slot >> 3) & 3, j = slot & 7;
        int chs = (jtype == 0) ? (slot >> 5) : 0;
        float v = 0.f;
        if (j < 7) {
            int c = chs * 28 + scg * 7 + j;      // CTA-local col
            int ul = c >> 2, g = c & 3, u = ubase + ul;
            if (u < UU) {
                if (jtype == 0)      v = Wh0[(size_t)k * GG + g * UU + u];
                else if (jtype == 1) v = (k < 400) ? Wx1[(size_t)k * GG + g * UU + u]
                                                   : Wh1[(size_t)(k - 400) * GG + g * UU + u];
                else                 v = (k < 400) ? Wx2[(size_t)k * GG + g * UU + u]
                                                   : Wh2[(size_t)(k - 400) * GG + g * UU + u];
            }
        }
        *(float*)(wsm + (size_t)k * rowB + slot * 4) = v;
    }
    if (jtype == 0) {
        for (int idx = tid; idx < 3 * 64; idx += 256) {
            int r = idx >> 6, slot = idx & 63;
            int scg = (slot >> 3) & 3, j = slot & 7, chs = slot >> 5;
            float v = 0.f;
            if (j < 7) {
                int c = chs * 28 + scg * 7 + j;
                int ul = c >> 2, g = c & 3, u = ubase + ul;
                if (u < UU) v = Wx0[(size_t)r * GG + g * UU + u];
            }
            *(float*)(waux + r * 256 + slot * 4) = v;
        }
    }

    // ---- gate-cell constants (cells = nu*32; guard real units) ----
    const int ncells = nu * 32;
    const int nslots = (ncells > 256) ? 2 : 1;
    float pi_r[2], pf_r[2], po_r[2];
    ull   bz[2][4];
    float cc[2][2];
    int   cu[2], cpb[2];
    bool  cok[2];
#pragma unroll
    for (int q = 0; q < 2; q++) {
        cok[q] = false; cu[q] = ubase; cpb[q] = 0;
        pi_r[q] = pf_r[q] = po_r[q] = 0.f;
        bz[q][0] = bz[q][1] = bz[q][2] = bz[q][3] = 0ull;
        cc[q][0] = cc[q][1] = 0.f;
        int cell = tid + q * 256;
        if (q < nslots && cell < ncells) {
            int ul = cell >> 5, pb = cell & 31, u = ubase + ul;
            cu[q] = u; cpb[q] = pb;
            if (u < UU) {
                cok[q] = true;
                pi_r[q] = pi[jtype * UU + u];
                pf_r[q] = pf[jtype * UU + u];
                po_r[q] = po[jtype * UU + u];
                for (int g = 0; g < 4; g++)
                    bz[q][g] = dup2(bb[jtype * GG + g * UU + u]);
            }
        }
    }

    // ---- compute-warp mapping ----
    int sl, chalf;
    if (jtype == 0) { chalf = wid >> 2; sl = wid & 3; }   // 2 halves x 4 slices
    else            { chalf = 0;        sl = wid;     }   // 8 slices
    const char* wrow0 = wsm + (size_t)(sl * 100) * rowB + chalf * 128 + cg * 32;
    const char* wauxp = waux + chalf * 128 + cg * 32;
    const int cpbase = chalf * 28 + cg * 7;               // first real col

    const unsigned base = g_flags[cta];
    __syncthreads();

    for (int s = 0; s < NSTEPS; s++) {
        const int t = s - jtype;
        const bool act = (t >= 0) && (t < TT);

        ull acc[7][4];
#pragma unroll
        for (int c = 0; c < 7; c++)
#pragma unroll
            for (int p = 0; p < 4; p++) acc[c][p] = 0ull;

        if (act) {
            const float* hsrc = nullptr;
            if (jtype == 0) {
                if (t > 0) hsrc = g_h0 + ((size_t)(t - 1) * UU + sl * 100) * BB;
            } else {
                if (sl < 4) {
                    hsrc = ((jtype == 1) ? g_h0 : g_h1) + ((size_t)t * UU + sl * 100) * BB;
                } else if (t > 0) {
                    hsrc = ((jtype == 1) ? g_h1 : g_h2) + ((size_t)(t - 1) * UU + (sl - 4) * 100) * BB;
                }
            }
            if (hsrc) {
                if (jtype == 0) accum100<256>(acc, wrow0, hsrc, pg);
                else            accum100<128>(acc, wrow0, hsrc, pg);
            }
            // folded L0 input projection: slice-3 warps add the 3 x-rows
            if (jtype == 0 && sl == 3)
                accum3(acc, wauxp, g_xaux + (size_t)t * (3 * BB), pg);

            // partial-sum store: red[sl][col][pair]
            ull* rp = red + ((size_t)sl * ncolsTot + cpbase) * 32 + pg * 4;
#pragma unroll
            for (int c = 0; c < 7; c++) {
                ulonglong2 s0; s0.x = acc[c][0]; s0.y = acc[c][1];
                ulonglong2 s1; s1.x = acc[c][2]; s1.y = acc[c][3];
                *(ulonglong2*)(rp + (size_t)c * 32)     = s0;
                *(ulonglong2*)(rp + (size_t)c * 32 + 2) = s1;
            }
        }
        __syncthreads();

        // gate phase: register-resident cells
        if (act) {
#pragma unroll
            for (int q = 0; q < 2; q++) {
                if (q < nslots && cok[q]) {
                    int ul4 = (cu[q] - ubase) << 2;
                    ull z[4];
#pragma unroll
                    for (int g = 0; g < 4; g++) {
                        ull zz = bz[q][g];
                        for (int s2 = 0; s2 < nslice; s2++)
                            zz = add2(zz, red[((size_t)s2 * ncolsTot + ul4 + g) * 32 + cpb[q]]);
                        z[g] = zz;
                    }
                    float* hout = ((jtype == 0) ? g_h0 : (jtype == 1) ? g_h1 : g_h2)
                                  + ((size_t)t * UU + cu[q]) * BB + 2 * cpb[q];
                    cell2(z, cc[q][0], cc[q][1], pi_r[q], pf_r[q], po_r[q], hout);
                }
            }
        }
        __syncthreads();   // all CTA stores done before release

        if (s < NSTEPS - 1) {
            unsigned tgt = base + (unsigned)s + 1u;
            if (tid == 0) st_rel(&g_flags[cta], tgt);
            if (tid < 32) {
                for (;;) {
                    bool ok = true;
                    for (int i = lane; i < NCTA_W; i += 32)
                        if (ld_acq(&g_flags[i]) < tgt) ok = false;
                    if (__all_sync(0xffffffffu, ok)) break;
                    __nanosleep(32);
                }
            }
            __syncthreads();
        }
    }
}

// ---------------- final projection ------------------------------------------
__global__ void final_kernel(const float* __restrict__ Wd,
                             const float* __restrict__ bd,
                             float* __restrict__ out)
{
    int t = blockIdx.x;
    int tid = threadIdx.x;  // 192
    __shared__ float wds[UU * FF];
    for (int i = tid; i < UU * FF; i += 192) wds[i] = Wd[i];
    __syncthreads();
    int b = tid / FF, f = tid % FF;
    const float* h = g_h2 + (size_t)t * UU * BB;
    float acc = bd[f];
#pragma unroll 4
    for (int u = 0; u < UU; u++)
        acc += h[(size_t)u * BB + b] * wds[u * FF + f];
    out[(size_t)b * (TT * FF) + t * FF + f] = acc;
}

// ---------------- launch -----------------------------------------------------
extern "C" void kernel_launch(void* const* d_in, const int* in_sizes, int n_in,
                              void* d_out, int out_size)
{
    (void)in_sizes; (void)n_in; (void)out_size;
    const float* x   = (const float*)d_in[0];
    const float* Wx0 = (const float*)d_in[1];
    const float* Wx1 = (const float*)d_in[2];
    const float* Wx2 = (const float*)d_in[3];
    const float* Wh  = (const float*)d_in[4];
    const float* bb  = (const float*)d_in[5];
    const float* pi  = (const float*)d_in[6];
    const float* pf  = (const float*)d_in[7];
    const float* po  = (const float*)d_in[8];
    const float* Wd  = (const float*)d_in[9];
    const float* bd  = (const float*)d_in[10];
    float* out = (float*)d_out;

    cudaFuncSetAttribute(wave_kernel, cudaFuncAttributeMaxDynamicSharedMemorySize, WAVE_SMEM);

    // transpose x to [t][d][b] (input projection folded into the wave)
    xt_kernel<<<TT, 192>>>(x);
    // fused 3-layer wavefront (702 steps, one grid barrier per step, 145 SMs)
    wave_kernel<<<NCTA_W, 256, WAVE_SMEM>>>(Wx0, Wx1, Wx2, Wh, bb, pi, pf, po);
    // output projection
    final_kernel<<<TT, 192>>>(Wd, bd, out);
}

// round 15
// speedup vs baseline: 1.1196x; 1.1196x over previous
#include <cuda_runtime.h>
#include <cstdint>
#include <cstddef>

// Problem dims
#define TT 700
#define BB 64
#define UU 400
#define GG 1600   // 4*U
#define FF 3
#define NSTEPS 702    // wavefront: L0@s, L1@s-1, L2@s-2
#define NCTA_W 125    // 25 L0 (16 units) + 50 L1 (8 units) + 50 L2 (8 units)

typedef unsigned long long ull;

// ---------------- static device scratch -------------------------------------
__device__ float g_xaux[(size_t)TT * 3 * BB];   // transposed input [t][d][b]
__device__ float g_h0[(size_t)TT * UU * BB];    // [t][u][b]
__device__ float g_h1[(size_t)TT * UU * BB];
__device__ float g_h2[(size_t)TT * UU * BB];
__device__ unsigned g_flags[NCTA_W];            // zero-init, monotonic barrier counters

// ---------------- helpers ----------------------------------------------------
__device__ __forceinline__ unsigned ld_acq(const unsigned* p) {
    unsigned v;
    asm volatile("ld.acquire.gpu.u32 %0, [%1];" : "=r"(v) : "l"(p) : "memory");
    return v;
}
__device__ __forceinline__ void st_rel(unsigned* p, unsigned v) {
    asm volatile("st.release.gpu.u32 [%0], %1;" :: "l"(p), "r"(v) : "memory");
}
__device__ __forceinline__ void ffma2(ull& d, ull a, ull b) {
    asm("fma.rn.f32x2 %0, %1, %2, %0;" : "+l"(d) : "l"(a), "l"(b));
}
__device__ __forceinline__ ull add2(ull a, ull b) {
    ull r; asm("add.rn.f32x2 %0, %1, %2;" : "=l"(r) : "l"(a), "l"(b)); return r;
}
__device__ __forceinline__ ull dup2(float w) {
    ull r; asm("mov.b64 %0, {%1, %1};" : "=l"(r) : "f"(w)); return r;
}
__device__ __forceinline__ ull pack2(float lo, float hi) {
    ull r; asm("mov.b64 %0, {%1, %2};" : "=l"(r) : "f"(lo), "f"(hi)); return r;
}
__device__ __forceinline__ float f2lo(ull v){ return __int_as_float((int)(unsigned)v); }
__device__ __forceinline__ float f2hi(ull v){ return __int_as_float((int)(v >> 32)); }
__device__ __forceinline__ float sigm(float x) { return 1.0f / (1.0f + __expf(-x)); }
__device__ __forceinline__ float tanh_fast(float x) {
    return 1.0f - 2.0f / (__expf(2.0f * x) + 1.0f);
}

// ---------------- input transpose: x[b][t][d] -> g_xaux[t][d][b] -------------
__global__ void xt_kernel(const float* __restrict__ x)
{
    int t = blockIdx.x;
    int tid = threadIdx.x;          // 192 = 64 b * 3 d
    int b = tid / 3, d = tid % 3;
    g_xaux[(size_t)t * (3 * BB) + d * BB + b] = x[(size_t)b * (TT * FF) + t * FF + d];
}

// ---------------- fused 3-layer wavefront (R13 core + dataflow barriers) ------
// 125 CTAs x 256 threads, persistent, 702 steps.
//   cta  0..24 : L0, 16 units (64 cols), k=400(+3 aux). 2 col-halves x 4 k-slices.
//   cta 25..74 : L1,  8 units (32 cols), k=800. 8 k-slices(100).
//   cta 75..124: L2,  8 units (32 cols), k=800. 8 k-slices(100).
// Dataflow barrier: each CTA polls ONLY its dependency range —
//   L0: flags[0,25)   (needs h0[t-1] only)
//   L1: flags[0,75)   (needs h0[t], h1[t-1])
//   L2: flags[25,125) (needs h1[t], h2[t-1])
// Acyclic dependency order -> no deadlock; h histories stored per-t -> a layer
// running ahead overwrites nothing a consumer still needs.
#define WSM_BYTES 102400
#define RED_BYTES 65536
#define WAVE_SMEM (WSM_BYTES + RED_BYTES + 768)

template<int NC>   // 64 (L0) or 32 (L1/2)
__device__ __forceinline__ void accum100(ull (&acc)[8][4],
                                         const float* __restrict__ wrow0,
                                         const float* __restrict__ hsrc,
                                         int pg)
{
    const char* hp = (const char*)hsrc + pg * 32;   // this thread's 4 pairs
    ulonglong2 hb[2][4][2];                          // [buf][row][half]
#pragma unroll
    for (int j = 0; j < 4; j++) {
        hb[0][j][0] = *(const ulonglong2*)(hp + j * 256);
        hb[0][j][1] = *(const ulonglong2*)(hp + j * 256 + 16);
    }
    const float* wrow = wrow0;
#pragma unroll 2
    for (int rc = 0; rc < 100; rc += 4) {
        int cur = (rc >> 2) & 1;
        if (rc < 96) {
            int nxt = cur ^ 1;
#pragma unroll
            for (int j = 0; j < 4; j++) {
                hb[nxt][j][0] = *(const ulonglong2*)(hp + (rc + 4 + j) * 256);
                hb[nxt][j][1] = *(const ulonglong2*)(hp + (rc + 4 + j) * 256 + 16);
            }
        }
#pragma unroll
        for (int j = 0; j < 4; j++) {
            float4 wa = *(const float4*)(wrow);
            float4 wb = *(const float4*)(wrow + 4);
            ull w0 = dup2(wa.x), w1 = dup2(wa.y), w2 = dup2(wa.z), w3 = dup2(wa.w);
            ull w4 = dup2(wb.x), w5 = dup2(wb.y), w6 = dup2(wb.z), w7 = dup2(wb.w);
            ulonglong2 hA = hb[cur][j][0];
            ulonglong2 hB = hb[cur][j][1];
            ffma2(acc[0][0], hA.x, w0); ffma2(acc[0][1], hA.y, w0);
            ffma2(acc[0][2], hB.x, w0); ffma2(acc[0][3], hB.y, w0);
            ffma2(acc[1][0], hA.x, w1); ffma2(acc[1][1], hA.y, w1);
            ffma2(acc[1][2], hB.x, w1); ffma2(acc[1][3], hB.y, w1);
            ffma2(acc[2][0], hA.x, w2); ffma2(acc[2][1], hA.y, w2);
            ffma2(acc[2][2], hB.x, w2); ffma2(acc[2][3], hB.y, w2);
            ffma2(acc[3][0], hA.x, w3); ffma2(acc[3][1], hA.y, w3);
            ffma2(acc[3][2], hB.x, w3); ffma2(acc[3][3], hB.y, w3);
            ffma2(acc[4][0], hA.x, w4); ffma2(acc[4][1], hA.y, w4);
            ffma2(acc[4][2], hB.x, w4); ffma2(acc[4][3], hB.y, w4);
            ffma2(acc[5][0], hA.x, w5); ffma2(acc[5][1], hA.y, w5);
            ffma2(acc[5][2], hB.x, w5); ffma2(acc[5][3], hB.y, w5);
            ffma2(acc[6][0], hA.x, w6); ffma2(acc[6][1], hA.y, w6);
            ffma2(acc[6][2], hB.x, w6); ffma2(acc[6][3], hB.y, w6);
            ffma2(acc[7][0], hA.x, w7); ffma2(acc[7][1], hA.y, w7);
            ffma2(acc[7][2], hB.x, w7); ffma2(acc[7][3], hB.y, w7);
            wrow += NC;
        }
    }
}

// 3 aux rows (input x) — same layout as h rows (256 B stride)
__device__ __forceinline__ void accum3(ull (&acc)[8][4],
                                       const float* __restrict__ wauxp,  // + col offset
                                       const float* __restrict__ xsrc,   // g_xaux + t*192
                                       int pg)
{
    const char* hp = (const char*)xsrc + pg * 32;
#pragma unroll
    for (int j = 0; j < 3; j++) {
        ulonglong2 hA = *(const ulonglong2*)(hp + j * 256);
        ulonglong2 hB = *(const ulonglong2*)(hp + j * 256 + 16);
        float4 wa = *(const float4*)(wauxp + j * 64);
        float4 wb = *(const float4*)(wauxp + j * 64 + 4);
        ull w0 = dup2(wa.x), w1 = dup2(wa.y), w2 = dup2(wa.z), w3 = dup2(wa.w);
        ull w4 = dup2(wb.x), w5 = dup2(wb.y), w6 = dup2(wb.z), w7 = dup2(wb.w);
        ffma2(acc[0][0], hA.x, w0); ffma2(acc[0][1], hA.y, w0);
        ffma2(acc[0][2], hB.x, w0); ffma2(acc[0][3], hB.y, w0);
        ffma2(acc[1][0], hA.x, w1); ffma2(acc[1][1], hA.y, w1);
        ffma2(acc[1][2], hB.x, w1); ffma2(acc[1][3], hB.y, w1);
        ffma2(acc[2][0], hA.x, w2); ffma2(acc[2][1], hA.y, w2);
        ffma2(acc[2][2], hB.x, w2); ffma2(acc[2][3], hB.y, w2);
        ffma2(acc[3][0], hA.x, w3); ffma2(acc[3][1], hA.y, w3);
        ffma2(acc[3][2], hB.x, w3); ffma2(acc[3][3], hB.y, w3);
        ffma2(acc[4][0], hA.x, w4); ffma2(acc[4][1], hA.y, w4);
        ffma2(acc[4][2], hB.x, w4); ffma2(acc[4][3], hB.y, w4);
        ffma2(acc[5][0], hA.x, w5); ffma2(acc[5][1], hA.y, w5);
        ffma2(acc[5][2], hB.x, w5); ffma2(acc[5][3], hB.y, w5);
        ffma2(acc[6][0], hA.x, w6); ffma2(acc[6][1], hA.y, w6);
        ffma2(acc[6][2], hB.x, w6); ffma2(acc[6][3], hB.y, w6);
        ffma2(acc[7][0], hA.x, w7); ffma2(acc[7][1], hA.y, w7);
        ffma2(acc[7][2], hB.x, w7); ffma2(acc[7][3], hB.y, w7);
    }
}

// LSTM cell, one unit, two batches; z packed f32x2 per gate; c in-place.
__device__ __forceinline__ void cell2(const ull z[4], float& c0, float& c1,
                                      float piv, float pfv, float pov,
                                      float* __restrict__ outp)
{
    float zi0 = f2lo(z[0]), zi1 = f2hi(z[0]);
    float zf0 = f2lo(z[1]), zf1 = f2hi(z[1]);
    float zg0 = f2lo(z[2]), zg1 = f2hi(z[2]);
    float zo0 = f2lo(z[3]), zo1 = f2hi(z[3]);

    float i0 = sigm(zi0 + piv * c0);
    float f0 = sigm(zf0 + pfv * c0);
    float cn0 = f0 * c0 + i0 * tanh_fast(zg0);
    float o0 = sigm(zo0 + pov * cn0);
    float h0 = o0 * tanh_fast(cn0);
    c0 = cn0;

    float i1 = sigm(zi1 + piv * c1);
    float f1 = sigm(zf1 + pfv * c1);
    float cn1 = f1 * c1 + i1 * tanh_fast(zg1);
    float o1 = sigm(zo1 + pov * cn1);
    float h1 = o1 * tanh_fast(cn1);
    c1 = cn1;

    *(ull*)outp = pack2(h0, h1);
}

__global__ void __launch_bounds__(256, 1) wave_kernel(const float* __restrict__ Wx0,
                                                      const float* __restrict__ Wx1,
                                                      const float* __restrict__ Wx2,
                                                      const float* __restrict__ Wh,
                                                      const float* __restrict__ bb,
                                                      const float* __restrict__ pi,
                                                      const float* __restrict__ pf,
                                                      const float* __restrict__ po)
{
    extern __shared__ char smraw[];
    float* wsm  = (float*)smraw;                           // [krows][ncols] fp32
    ull*   red  = (ull*)(smraw + WSM_BYTES);               // [nslice][ncolsTot][32 pairs]
    float* waux = (float*)(smraw + WSM_BYTES + RED_BYTES); // [3][64] L0 x-row weights

    const int tid  = threadIdx.x;
    const int cta  = blockIdx.x;
    const int wid  = tid >> 5;
    const int lane = tid & 31;
    const int cg   = lane & 3;     // col-group (8 cols)
    const int pg   = lane >> 2;    // pair-group (4 pairs)

    int jtype, ubase, nu;
    if (cta < 25)      { jtype = 0; ubase = cta * 16;        nu = 16; }
    else if (cta < 75) { jtype = 1; ubase = (cta - 25) * 8;  nu = 8;  }
    else               { jtype = 2; ubase = (cta - 75) * 8;  nu = 8;  }
    const int ncols  = nu * 4;                  // 64 or 32
    const int nslice = (jtype == 0) ? 4 : 8;

    // dataflow-barrier poll range (dependency CTAs only; acyclic -> deadlock-free)
    int plo, phi;
    if (jtype == 0)      { plo = 0;  phi = 25;  }
    else if (jtype == 1) { plo = 0;  phi = 75;  }
    else                 { plo = 25; phi = 125; }

    const float* Wh0 = Wh;
    const float* Wh1 = Wh + (size_t)UU * GG;
    const float* Wh2 = Wh + (size_t)2 * UU * GG;

    // ---- weight fill: 25600 fp32 (+ L0 aux rows) ----
    for (int idx = tid; idx < 25600; idx += 256) {
        int k, c;
        if (jtype == 0) { k = idx >> 6; c = idx & 63; }
        else            { k = idx >> 5; c = idx & 31; }
        int ul = c >> 2, g = c & 3, u = ubase + ul;
        float v;
        if (jtype == 0)      v = Wh0[(size_t)k * GG + g * UU + u];
        else if (jtype == 1) v = (k < 400) ? Wx1[(size_t)k * GG + g * UU + u]
                                           : Wh1[(size_t)(k - 400) * GG + g * UU + u];
        else                 v = (k < 400) ? Wx2[(size_t)k * GG + g * UU + u]
                                           : Wh2[(size_t)(k - 400) * GG + g * UU + u];
        wsm[idx] = v;
    }
    if (jtype == 0) {
        for (int idx = tid; idx < 3 * 64; idx += 256) {
            int j = idx >> 6, c = idx & 63;
            int ul = c >> 2, g = c & 3, u = ubase + ul;
            waux[idx] = Wx0[(size_t)j * GG + g * UU + u];
        }
    }

    // ---- gate-cell constants (1 or 2 cells per thread, all valid) ----
    const int nslots = (jtype == 0) ? 2 : 1;
    float pi_r[2], pf_r[2], po_r[2];
    ull   bz[2][4];
    float cc[2][2];
    int   cu[2], cpb[2];
#pragma unroll
    for (int q = 0; q < 2; q++) {
        cu[q] = ubase; cpb[q] = 0;
        pi_r[q] = pf_r[q] = po_r[q] = 0.f;
        bz[q][0] = bz[q][1] = bz[q][2] = bz[q][3] = 0ull;
        cc[q][0] = cc[q][1] = 0.f;
        if (q < nslots) {
            int cell = tid + q * 256;
            int ul = cell >> 5, pb = cell & 31, u = ubase + ul;
            cu[q] = u; cpb[q] = pb;
            pi_r[q] = pi[jtype * UU + u];
            pf_r[q] = pf[jtype * UU + u];
            po_r[q] = po[jtype * UU + u];
            for (int g = 0; g < 4; g++)
                bz[q][g] = dup2(bb[jtype * GG + g * UU + u]);
        }
    }

    // ---- compute-warp mapping ----
    int sl, chalf;
    if (jtype == 0) { chalf = wid >> 2; sl = wid & 3; }   // 2 halves x 4 slices
    else            { chalf = 0;        sl = wid;     }   // 8 slices
    const int mycol0 = chalf * 32 + cg * 8;
    const float* wrow0 = wsm + (size_t)(sl * 100) * ncols + mycol0;
    const float* wauxp = waux + mycol0;

    const unsigned base = g_flags[cta];
    __syncthreads();

    for (int s = 0; s < NSTEPS; s++) {
        const int t = s - jtype;
        const bool act = (t >= 0) && (t < TT);

        ull acc[8][4];
#pragma unroll
        for (int c = 0; c < 8; c++)
#pragma unroll
            for (int p = 0; p < 4; p++) acc[c][p] = 0ull;

        if (act) {
            const float* hsrc = nullptr;
            if (jtype == 0) {
                if (t > 0) hsrc = g_h0 + ((size_t)(t - 1) * UU + sl * 100) * BB;
            } else {
                if (sl < 4) {
                    hsrc = ((jtype == 1) ? g_h0 : g_h1) + ((size_t)t * UU + sl * 100) * BB;
                } else if (t > 0) {
                    hsrc = ((jtype == 1) ? g_h1 : g_h2) + ((size_t)(t - 1) * UU + (sl - 4) * 100) * BB;
                }
            }
            if (hsrc) {
                if (jtype == 0) accum100<64>(acc, wrow0, hsrc, pg);
                else            accum100<32>(acc, wrow0, hsrc, pg);
            }
            // folded L0 input projection: slice-3 warps add the 3 x-rows
            if (jtype == 0 && sl == 3)
                accum3(acc, wauxp, g_xaux + (size_t)t * (3 * BB), pg);

            // partial-sum store: red[sl][col][pair], ull elements
            const int ncolsTot = (jtype == 0) ? 64 : 32;
            ull* rp = red + ((size_t)sl * ncolsTot + mycol0) * 32 + pg * 4;
#pragma unroll
            for (int c = 0; c < 8; c++) {
                ulonglong2 s0; s0.x = acc[c][0]; s0.y = acc[c][1];
                ulonglong2 s1; s1.x = acc[c][2]; s1.y = acc[c][3];
                *(ulonglong2*)(rp + (size_t)c * 32)     = s0;
                *(ulonglong2*)(rp + (size_t)c * 32 + 2) = s1;
            }
        }
        __syncthreads();

        // gate phase: register-resident cells, bias from registers
        if (act) {
            const int ncolsTot = (jtype == 0) ? 64 : 32;
#pragma unroll
            for (int q = 0; q < 2; q++) {
                if (q < nslots) {
                    int ul4 = (cu[q] - ubase) << 2;
                    ull z[4];
#pragma unroll
                    for (int g = 0; g < 4; g++) {
                        ull zz = bz[q][g];
                        for (int s2 = 0; s2 < nslice; s2++)
                            zz = add2(zz, red[((size_t)s2 * ncolsTot + ul4 + g) * 32 + cpb[q]]);
                        z[g] = zz;
                    }
                    float* hout = ((jtype == 0) ? g_h0 : (jtype == 1) ? g_h1 : g_h2)
                                  + ((size_t)t * UU + cu[q]) * BB + 2 * cpb[q];
                    cell2(z, cc[q][0], cc[q][1], pi_r[q], pf_r[q], po_r[q], hout);
                }
            }
        }
        __syncthreads();   // all CTA stores done before release

        if (s < NSTEPS - 1) {
            unsigned tgt = base + (unsigned)s + 1u;
            if (tid == 0) st_rel(&g_flags[cta], tgt);
            if (tid < 32) {
                // dataflow poll: only dependency CTAs' flags
                for (;;) {
                    bool ok = true;
                    for (int i = plo + lane; i < phi; i += 32)
                        if (ld_acq(&g_flags[i]) < tgt) ok = false;
                    if (__all_sync(0xffffffffu, ok)) break;
                    __nanosleep(32);
                }
            }
            __syncthreads();
        }
    }
}

// ---------------- final projection ------------------------------------------
__global__ void final_kernel(const float* __restrict__ Wd,
                             const float* __restrict__ bd,
                             float* __restrict__ out)
{
    int t = blockIdx.x;
    int tid = threadIdx.x;  // 192
    __shared__ float wds[UU * FF];
    for (int i = tid; i < UU * FF; i += 192) wds[i] = Wd[i];
    __syncthreads();
    int b = tid / FF, f = tid % FF;
    const float* h = g_h2 + (size_t)t * UU * BB;
    float acc = bd[f];
#pragma unroll 4
    for (int u = 0; u < UU; u++)
        acc += h[(size_t)u * BB + b] * wds[u * FF + f];
    out[(size_t)b * (TT * FF) + t * FF + f] = acc;
}

// ---------------- launch -----------------------------------------------------
extern "C" void kernel_launch(void* const* d_in, const int* in_sizes, int n_in,
                              void* d_out, int out_size)
{
    (void)in_sizes; (void)n_in; (void)out_size;
    const float* x   = (const float*)d_in[0];
    const float* Wx0 = (const float*)d_in[1];
    const float* Wx1 = (const float*)d_in[2];
    const float* Wx2 = (const float*)d_in[3];
    const float* Wh  = (const float*)d_in[4];
    const float* bb  = (const float*)d_in[5];
    const float* pi  = (const float*)d_in[6];
    const float* pf  = (const float*)d_in[7];
    const float* po  = (const float*)d_in[8];
    const float* Wd  = (const float*)d_in[9];
    const float* bd  = (const float*)d_in[10];
    float* out = (float*)d_out;

    cudaFuncSetAttribute(wave_kernel, cudaFuncAttributeMaxDynamicSharedMemorySize, WAVE_SMEM);

    // transpose x to [t][d][b] (input projection folded into the wave)
    xt_kernel<<<TT, 192>>>(x);
    // fused 3-layer wavefront with layer-local dataflow barriers
    wave_kernel<<<NCTA_W, 256, WAVE_SMEM>>>(Wx0, Wx1, Wx2, Wh, bb, pi, pf, po);
    // output projection
    final_kernel<<<TT, 192>>>(Wd, bd, out);
}

// round 16
// speedup vs baseline: 1.1847x; 1.0581x over previous
#include <cuda_runtime.h>
#include <cstdint>
#include <cstddef>

// Problem dims
#define TT 700
#define BB 64
#define UU 400
#define GG 1600   // 4*U
#define FF 3
#define NSTEPS 702    // wavefront: L0@s, L1@s-1, L2@s-2
#define NCTA_W 125    // 25 L0 (16 units) + 50 L1 (8 units) + 50 L2 (8 units)

typedef unsigned long long ull;

// ---------------- static device scratch -------------------------------------
__device__ float g_xaux[(size_t)TT * 3 * BB];   // transposed input [t][d][b]
__device__ float g_h0[(size_t)TT * UU * BB];    // [t][u][b]
__device__ float g_h1[(size_t)TT * UU * BB];
__device__ float g_h2[(size_t)TT * UU * BB];
__device__ unsigned g_flags[NCTA_W];            // zero-init, monotonic barrier counters

// ---------------- helpers ----------------------------------------------------
__device__ __forceinline__ unsigned ld_acq(const unsigned* p) {
    unsigned v;
    asm volatile("ld.acquire.gpu.u32 %0, [%1];" : "=r"(v) : "l"(p) : "memory");
    return v;
}
__device__ __forceinline__ void st_rel(unsigned* p, unsigned v) {
    asm volatile("st.release.gpu.u32 [%0], %1;" :: "l"(p), "r"(v) : "memory");
}
__device__ __forceinline__ void ffma2(ull& d, ull a, ull b) {
    asm("fma.rn.f32x2 %0, %1, %2, %0;" : "+l"(d) : "l"(a), "l"(b));
}
__device__ __forceinline__ ull add2(ull a, ull b) {
    ull r; asm("add.rn.f32x2 %0, %1, %2;" : "=l"(r) : "l"(a), "l"(b)); return r;
}
__device__ __forceinline__ ull dup2(float w) {
    ull r; asm("mov.b64 %0, {%1, %1};" : "=l"(r) : "f"(w)); return r;
}
__device__ __forceinline__ ull pack2(float lo, float hi) {
    ull r; asm("mov.b64 %0, {%1, %2};" : "=l"(r) : "f"(lo), "f"(hi)); return r;
}
__device__ __forceinline__ float f2lo(ull v){ return __int_as_float((int)(unsigned)v); }
__device__ __forceinline__ float f2hi(ull v){ return __int_as_float((int)(v >> 32)); }
// gate nonlinearities on the serialized path: MUFU exp + approx reciprocal
// (<=2 ulp; ~1e-7 contribution vs 1e-3 budget)
__device__ __forceinline__ float sigm(float x) {
    return __fdividef(1.0f, 1.0f + __expf(-x));
}
__device__ __forceinline__ float tanh_fast(float x) {
    return 1.0f - __fdividef(2.0f, __expf(2.0f * x) + 1.0f);
}

// ---------------- input transpose: x[b][t][d] -> g_xaux[t][d][b] -------------
__global__ void xt_kernel(const float* __restrict__ x)
{
    int t = blockIdx.x;
    int tid = threadIdx.x;          // 192 = 64 b * 3 d
    int b = tid / 3, d = tid % 3;
    g_xaux[(size_t)t * (3 * BB) + d * BB + b] = x[(size_t)b * (TT * FF) + t * FF + d];
}

// ---------------- fused 3-layer wavefront (R15 core, gate-chain trims) --------
// 125 CTAs x 256 threads, persistent, 702 steps.
//   cta  0..24 : L0, 16 units (64 cols), k=400(+3 aux). 2 col-halves x 4 k-slices.
//   cta 25..74 : L1,  8 units (32 cols), k=800. 8 k-slices(100).
//   cta 75..124: L2,  8 units (32 cols), k=800. 8 k-slices(100).
// Dataflow barrier: L0 polls flags[0,25); L1 [0,75); L2 [25,125).
#define WSM_BYTES 102400
#define RED_BYTES 65536
#define WAVE_SMEM (WSM_BYTES + RED_BYTES + 768)

template<int NC>   // 64 (L0) or 32 (L1/2)
__device__ __forceinline__ void accum100(ull (&acc)[8][4],
                                         const float* __restrict__ wrow0,
                                         const float* __restrict__ hsrc,
                                         int pg)
{
    const char* hp = (const char*)hsrc + pg * 32;   // this thread's 4 pairs
    ulonglong2 hb[2][4][2];                          // [buf][row][half]
#pragma unroll
    for (int j = 0; j < 4; j++) {
        hb[0][j][0] = *(const ulonglong2*)(hp + j * 256);
        hb[0][j][1] = *(const ulonglong2*)(hp + j * 256 + 16);
    }
    const float* wrow = wrow0;
#pragma unroll 2
    for (int rc = 0; rc < 100; rc += 4) {
        int cur = (rc >> 2) & 1;
        if (rc < 96) {
            int nxt = cur ^ 1;
#pragma unroll
            for (int j = 0; j < 4; j++) {
                hb[nxt][j][0] = *(const ulonglong2*)(hp + (rc + 4 + j) * 256);
                hb[nxt][j][1] = *(const ulonglong2*)(hp + (rc + 4 + j) * 256 + 16);
            }
        }
#pragma unroll
        for (int j = 0; j < 4; j++) {
            float4 wa = *(const float4*)(wrow);
            float4 wb = *(const float4*)(wrow + 4);
            ull w0 = dup2(wa.x), w1 = dup2(wa.y), w2 = dup2(wa.z), w3 = dup2(wa.w);
            ull w4 = dup2(wb.x), w5 = dup2(wb.y), w6 = dup2(wb.z), w7 = dup2(wb.w);
            ulonglong2 hA = hb[cur][j][0];
            ulonglong2 hB = hb[cur][j][1];
            ffma2(acc[0][0], hA.x, w0); ffma2(acc[0][1], hA.y, w0);
            ffma2(acc[0][2], hB.x, w0); ffma2(acc[0][3], hB.y, w0);
            ffma2(acc[1][0], hA.x, w1); ffma2(acc[1][1], hA.y, w1);
            ffma2(acc[1][2], hB.x, w1); ffma2(acc[1][3], hB.y, w1);
            ffma2(acc[2][0], hA.x, w2); ffma2(acc[2][1], hA.y, w2);
            ffma2(acc[2][2], hB.x, w2); ffma2(acc[2][3], hB.y, w2);
            ffma2(acc[3][0], hA.x, w3); ffma2(acc[3][1], hA.y, w3);
            ffma2(acc[3][2], hB.x, w3); ffma2(acc[3][3], hB.y, w3);
            ffma2(acc[4][0], hA.x, w4); ffma2(acc[4][1], hA.y, w4);
            ffma2(acc[4][2], hB.x, w4); ffma2(acc[4][3], hB.y, w4);
            ffma2(acc[5][0], hA.x, w5); ffma2(acc[5][1], hA.y, w5);
            ffma2(acc[5][2], hB.x, w5); ffma2(acc[5][3], hB.y, w5);
            ffma2(acc[6][0], hA.x, w6); ffma2(acc[6][1], hA.y, w6);
            ffma2(acc[6][2], hB.x, w6); ffma2(acc[6][3], hB.y, w6);
            ffma2(acc[7][0], hA.x, w7); ffma2(acc[7][1], hA.y, w7);
            ffma2(acc[7][2], hB.x, w7); ffma2(acc[7][3], hB.y, w7);
            wrow += NC;
        }
    }
}

// 3 aux rows (input x) — same layout as h rows (256 B stride)
__device__ __forceinline__ void accum3(ull (&acc)[8][4],
                                       const float* __restrict__ wauxp,  // + col offset
                                       const float* __restrict__ xsrc,   // g_xaux + t*192
                                       int pg)
{
    const char* hp = (const char*)xsrc + pg * 32;
#pragma unroll
    for (int j = 0; j < 3; j++) {
        ulonglong2 hA = *(const ulonglong2*)(hp + j * 256);
        ulonglong2 hB = *(const ulonglong2*)(hp + j * 256 + 16);
        float4 wa = *(const float4*)(wauxp + j * 64);
        float4 wb = *(const float4*)(wauxp + j * 64 + 4);
        ull w0 = dup2(wa.x), w1 = dup2(wa.y), w2 = dup2(wa.z), w3 = dup2(wa.w);
        ull w4 = dup2(wb.x), w5 = dup2(wb.y), w6 = dup2(wb.z), w7 = dup2(wb.w);
        ffma2(acc[0][0], hA.x, w0); ffma2(acc[0][1], hA.y, w0);
        ffma2(acc[0][2], hB.x, w0); ffma2(acc[0][3], hB.y, w0);
        ffma2(acc[1][0], hA.x, w1); ffma2(acc[1][1], hA.y, w1);
        ffma2(acc[1][2], hB.x, w1); ffma2(acc[1][3], hB.y, w1);
        ffma2(acc[2][0], hA.x, w2); ffma2(acc[2][1], hA.y, w2);
        ffma2(acc[2][2], hB.x, w2); ffma2(acc[2][3], hB.y, w2);
        ffma2(acc[3][0], hA.x, w3); ffma2(acc[3][1], hA.y, w3);
        ffma2(acc[3][2], hB.x, w3); ffma2(acc[3][3], hB.y, w3);
        ffma2(acc[4][0], hA.x, w4); ffma2(acc[4][1], hA.y, w4);
        ffma2(acc[4][2], hB.x, w4); ffma2(acc[4][3], hB.y, w4);
        ffma2(acc[5][0], hA.x, w5); ffma2(acc[5][1], hA.y, w5);
        ffma2(acc[5][2], hB.x, w5); ffma2(acc[5][3], hB.y, w5);
        ffma2(acc[6][0], hA.x, w6); ffma2(acc[6][1], hA.y, w6);
        ffma2(acc[6][2], hB.x, w6); ffma2(acc[6][3], hB.y, w6);
        ffma2(acc[7][0], hA.x, w7); ffma2(acc[7][1], hA.y, w7);
        ffma2(acc[7][2], hB.x, w7); ffma2(acc[7][3], hB.y, w7);
    }
}

// LSTM cell, one unit, two batches; z packed f32x2 per gate; c in-place.
__device__ __forceinline__ void cell2(const ull z[4], float& c0, float& c1,
                                      float piv, float pfv, float pov,
                                      float* __restrict__ outp)
{
    float zi0 = f2lo(z[0]), zi1 = f2hi(z[0]);
    float zf0 = f2lo(z[1]), zf1 = f2hi(z[1]);
    float zg0 = f2lo(z[2]), zg1 = f2hi(z[2]);
    float zo0 = f2lo(z[3]), zo1 = f2hi(z[3]);

    float i0 = sigm(zi0 + piv * c0);
    float f0 = sigm(zf0 + pfv * c0);
    float cn0 = f0 * c0 + i0 * tanh_fast(zg0);
    float o0 = sigm(zo0 + pov * cn0);
    float h0 = o0 * tanh_fast(cn0);
    c0 = cn0;

    float i1 = sigm(zi1 + piv * c1);
    float f1 = sigm(zf1 + pfv * c1);
    float cn1 = f1 * c1 + i1 * tanh_fast(zg1);
    float o1 = sigm(zo1 + pov * cn1);
    float h1 = o1 * tanh_fast(cn1);
    c1 = cn1;

    *(ull*)outp = pack2(h0, h1);
}

__global__ void __launch_bounds__(256, 1) wave_kernel(const float* __restrict__ Wx0,
                                                      const float* __restrict__ Wx1,
                                                      const float* __restrict__ Wx2,
                                                      const float* __restrict__ Wh,
                                                      const float* __restrict__ bb,
                                                      const float* __restrict__ pi,
                                                      const float* __restrict__ pf,
                                                      const float* __restrict__ po)
{
    extern __shared__ char smraw[];
    float* wsm  = (float*)smraw;                           // [krows][ncols] fp32
    ull*   red  = (ull*)(smraw + WSM_BYTES);               // [nslice][ncolsTot][32 pairs]
    float* waux = (float*)(smraw + WSM_BYTES + RED_BYTES); // [3][64] L0 x-row weights

    const int tid  = threadIdx.x;
    const int cta  = blockIdx.x;
    const int wid  = tid >> 5;
    const int lane = tid & 31;
    const int cg   = lane & 3;     // col-group (8 cols)
    const int pg   = lane >> 2;    // pair-group (4 pairs)

    int jtype, ubase, nu;
    if (cta < 25)      { jtype = 0; ubase = cta * 16;        nu = 16; }
    else if (cta < 75) { jtype = 1; ubase = (cta - 25) * 8;  nu = 8;  }
    else               { jtype = 2; ubase = (cta - 75) * 8;  nu = 8;  }
    const int ncols  = nu * 4;                  // 64 or 32
    const int nslice = (jtype == 0) ? 4 : 8;

    // dataflow-barrier poll range (dependency CTAs only; acyclic -> deadlock-free)
    int plo, phi;
    if (jtype == 0)      { plo = 0;  phi = 25;  }
    else if (jtype == 1) { plo = 0;  phi = 75;  }
    else                 { plo = 25; phi = 125; }

    const float* Wh0 = Wh;
    const float* Wh1 = Wh + (size_t)UU * GG;
    const float* Wh2 = Wh + (size_t)2 * UU * GG;

    // ---- weight fill: 25600 fp32 (+ L0 aux rows) ----
    for (int idx = tid; idx < 25600; idx += 256) {
        int k, c;
        if (jtype == 0) { k = idx >> 6; c = idx & 63; }
        else            { k = idx >> 5; c = idx & 31; }
        int ul = c >> 2, g = c & 3, u = ubase + ul;
        float v;
        if (jtype == 0)      v = Wh0[(size_t)k * GG + g * UU + u];
        else if (jtype == 1) v = (k < 400) ? Wx1[(size_t)k * GG + g * UU + u]
                                           : Wh1[(size_t)(k - 400) * GG + g * UU + u];
        else                 v = (k < 400) ? Wx2[(size_t)k * GG + g * UU + u]
                                           : Wh2[(size_t)(k - 400) * GG + g * UU + u];
        wsm[idx] = v;
    }
    if (jtype == 0) {
        for (int idx = tid; idx < 3 * 64; idx += 256) {
            int j = idx >> 6, c = idx & 63;
            int ul = c >> 2, g = c & 3, u = ubase + ul;
            waux[idx] = Wx0[(size_t)j * GG + g * UU + u];
        }
    }

    // ---- gate-cell constants (1 or 2 cells per thread, all valid) ----
    const int nslots = (jtype == 0) ? 2 : 1;
    float pi_r[2], pf_r[2], po_r[2];
    ull   bz[2][4];
    float cc[2][2];
    int   cu[2], cpb[2];
#pragma unroll
    for (int q = 0; q < 2; q++) {
        cu[q] = ubase; cpb[q] = 0;
        pi_r[q] = pf_r[q] = po_r[q] = 0.f;
        bz[q][0] = bz[q][1] = bz[q][2] = bz[q][3] = 0ull;
        cc[q][0] = cc[q][1] = 0.f;
        if (q < nslots) {
            int cell = tid + q * 256;
            int ul = cell >> 5, pb = cell & 31, u = ubase + ul;
            cu[q] = u; cpb[q] = pb;
            pi_r[q] = pi[jtype * UU + u];
            pf_r[q] = pf[jtype * UU + u];
            po_r[q] = po[jtype * UU + u];
            for (int g = 0; g < 4; g++)
                bz[q][g] = dup2(bb[jtype * GG + g * UU + u]);
        }
    }

    // ---- compute-warp mapping ----
    int sl, chalf;
    if (jtype == 0) { chalf = wid >> 2; sl = wid & 3; }   // 2 halves x 4 slices
    else            { chalf = 0;        sl = wid;     }   // 8 slices
    const int mycol0 = chalf * 32 + cg * 8;
    const float* wrow0 = wsm + (size_t)(sl * 100) * ncols + mycol0;
    const float* wauxp = waux + mycol0;

    const unsigned base = g_flags[cta];
    __syncthreads();

    for (int s = 0; s < NSTEPS; s++) {
        const int t = s - jtype;
        const bool act = (t >= 0) && (t < TT);

        ull acc[8][4];
#pragma unroll
        for (int c = 0; c < 8; c++)
#pragma unroll
            for (int p = 0; p < 4; p++) acc[c][p] = 0ull;

        if (act) {
            // folded L0 input projection FIRST: slice-3 warps front-load the
            // 3 x-rows so their extra LDG latency overlaps the main k-loop
            if (jtype == 0 && sl == 3)
                accum3(acc, wauxp, g_xaux + (size_t)t * (3 * BB), pg);

            const float* hsrc = nullptr;
            if (jtype == 0) {
                if (t > 0) hsrc = g_h0 + ((size_t)(t - 1) * UU + sl * 100) * BB;
            } else {
                if (sl < 4) {
                    hsrc = ((jtype == 1) ? g_h0 : g_h1) + ((size_t)t * UU + sl * 100) * BB;
                } else if (t > 0) {
                    hsrc = ((jtype == 1) ? g_h1 : g_h2) + ((size_t)(t - 1) * UU + (sl - 4) * 100) * BB;
                }
            }
            if (hsrc) {
                if (jtype == 0) accum100<64>(acc, wrow0, hsrc, pg);
                else            accum100<32>(acc, wrow0, hsrc, pg);
            }

            // partial-sum store: red[sl][col][pair], ull elements
            const int ncolsTot = (jtype == 0) ? 64 : 32;
            ull* rp = red + ((size_t)sl * ncolsTot + mycol0) * 32 + pg * 4;
#pragma unroll
            for (int c = 0; c < 8; c++) {
                ulonglong2 s0; s0.x = acc[c][0]; s0.y = acc[c][1];
                ulonglong2 s1; s1.x = acc[c][2]; s1.y = acc[c][3];
                *(ulonglong2*)(rp + (size_t)c * 32)     = s0;
                *(ulonglong2*)(rp + (size_t)c * 32 + 2) = s1;
            }
        }
        __syncthreads();

        // gate phase: register-resident cells, bias from registers
        if (act) {
            const int ncolsTot = (jtype == 0) ? 64 : 32;
#pragma unroll
            for (int q = 0; q < 2; q++) {
                if (q < nslots) {
                    int ul4 = (cu[q] - ubase) << 2;
                    const ull* rb = red + (size_t)(ul4 * 32) + cpb[q];
                    ull z[4];
#pragma unroll
                    for (int g = 0; g < 4; g++) {
                        ull zz = bz[q][g];
                        const ull* rp2 = rb + (size_t)g * 32;
                        for (int s2 = 0; s2 < nslice; s2++)
                            zz = add2(zz, rp2[(size_t)s2 * ncolsTot * 32]);
                        z[g] = zz;
                    }
                    float* hout = ((jtype == 0) ? g_h0 : (jtype == 1) ? g_h1 : g_h2)
                                  + ((size_t)t * UU + cu[q]) * BB + 2 * cpb[q];
                    cell2(z, cc[q][0], cc[q][1], pi_r[q], pf_r[q], po_r[q], hout);
                }
            }
        }
        __syncthreads();   // all CTA stores done before release

        if (s < NSTEPS - 1) {
            unsigned tgt = base + (unsigned)s + 1u;
            if (tid == 0) st_rel(&g_flags[cta], tgt);
            if (tid < 32) {
                // dataflow poll: only dependency CTAs' flags
                for (;;) {
                    bool ok = true;
                    for (int i = plo + lane; i < phi; i += 32)
                        if (ld_acq(&g_flags[i]) < tgt) ok = false;
                    if (__all_sync(0xffffffffu, ok)) break;
                    __nanosleep(16);
                }
            }
            __syncthreads();
        }
    }
}

// ---------------- final projection ------------------------------------------
__global__ void final_kernel(const float* __restrict__ Wd,
                             const float* __restrict__ bd,
                             float* __restrict__ out)
{
    int t = blockIdx.x;
    int tid = threadIdx.x;  // 192
    __shared__ float wds[UU * FF];
    for (int i = tid; i < UU * FF; i += 192) wds[i] = Wd[i];
    __syncthreads();
    int b = tid / FF, f = tid % FF;
    const float* h = g_h2 + (size_t)t * UU * BB;
    float acc = bd[f];
#pragma unroll 4
    for (int u = 0; u < UU; u++)
        acc += h[(size_t)u * BB + b] * wds[u * FF + f];
    out[(size_t)b * (TT * FF) + t * FF + f] = acc;
}

// ---------------- launch -----------------------------------------------------
extern "C" void kernel_launch(void* const* d_in, const int* in_sizes, int n_in,
                              void* d_out, int out_size)
{
    (void)in_sizes; (void)n_in; (void)out_size;
    const float* x   = (const float*)d_in[0];
    const float* Wx0 = (const float*)d_in[1];
    const float* Wx1 = (const float*)d_in[2];
    const float* Wx2 = (const float*)d_in[3];
    const float* Wh  = (const float*)d_in[4];
    const float* bb  = (const float*)d_in[5];
    const float* pi  = (const float*)d_in[6];
    const float* pf  = (const float*)d_in[7];
    const float* po  = (const float*)d_in[8];
    const float* Wd  = (const float*)d_in[9];
    const float* bd  = (const float*)d_in[10];
    float* out = (float*)d_out;

    cudaFuncSetAttribute(wave_kernel, cudaFuncAttributeMaxDynamicSharedMemorySize, WAVE_SMEM);

    // transpose x to [t][d][b] (input projection folded into the wave)
    xt_kernel<<<TT, 192>>>(x);
    // fused 3-layer wavefront with layer-local dataflow barriers
    wave_kernel<<<NCTA_W, 256, WAVE_SMEM>>>(Wx0, Wx1, Wx2, Wh, bb, pi, pf, po);
    // output projection
    final_kernel<<<TT, 192>>>(Wd, bd, out);
}

// round 17
// speedup vs baseline: 1.1863x; 1.0014x over previous
#include <cuda_runtime.h>
#include <cstdint>
#include <cstddef>

// Problem dims
#define TT 700
#define BB 64
#define UU 400
#define GG 1600   // 4*U
#define FF 3
#define NSTEPS 702    // wavefront: L0@s, L1@s-1, L2@s-2
#define NCTA_W 125    // 25 L0 (16 units) + 50 L1 (8 units) + 50 L2 (8 units)

typedef unsigned long long ull;

// ---------------- static device scratch -------------------------------------
__device__ float g_xaux[(size_t)TT * 3 * BB];   // transposed input [t][d][b]
__device__ float g_h0[(size_t)TT * UU * BB];    // [t][u][b]
__device__ float g_h1[(size_t)TT * UU * BB];
__device__ float g_h2[(size_t)TT * UU * BB];
__device__ unsigned g_flags[NCTA_W];            // zero-init, monotonic barrier counters

// ---------------- helpers ----------------------------------------------------
__device__ __forceinline__ unsigned ld_acq(const unsigned* p) {
    unsigned v;
    asm volatile("ld.acquire.gpu.u32 %0, [%1];" : "=r"(v) : "l"(p) : "memory");
    return v;
}
__device__ __forceinline__ void st_rel(unsigned* p, unsigned v) {
    asm volatile("st.release.gpu.u32 [%0], %1;" :: "l"(p), "r"(v) : "memory");
}
__device__ __forceinline__ void ffma2(ull& d, ull a, ull b) {
    asm("fma.rn.f32x2 %0, %1, %2, %0;" : "+l"(d) : "l"(a), "l"(b));
}
__device__ __forceinline__ ull add2(ull a, ull b) {
    ull r; asm("add.rn.f32x2 %0, %1, %2;" : "=l"(r) : "l"(a), "l"(b)); return r;
}
__device__ __forceinline__ ull dup2(float w) {
    ull r; asm("mov.b64 %0, {%1, %1};" : "=l"(r) : "f"(w)); return r;
}
__device__ __forceinline__ ull pack2(float lo, float hi) {
    ull r; asm("mov.b64 %0, {%1, %2};" : "=l"(r) : "f"(lo), "f"(hi)); return r;
}
__device__ __forceinline__ float f2lo(ull v){ return __int_as_float((int)(unsigned)v); }
__device__ __forceinline__ float f2hi(ull v){ return __int_as_float((int)(v >> 32)); }
// gate nonlinearities on the serialized path: MUFU exp + approx reciprocal
__device__ __forceinline__ float sigm(float x) {
    return __fdividef(1.0f, 1.0f + __expf(-x));
}
__device__ __forceinline__ float tanh_fast(float x) {
    return 1.0f - __fdividef(2.0f, __expf(2.0f * x) + 1.0f);
}

// ---------------- input transpose: x[b][t][d] -> g_xaux[t][d][b] -------------
__global__ void xt_kernel(const float* __restrict__ x)
{
    int t = blockIdx.x;
    int tid = threadIdx.x;          // 192 = 64 b * 3 d
    int b = tid / 3, d = tid % 3;
    g_xaux[(size_t)t * (3 * BB) + d * BB + b] = x[(size_t)b * (TT * FF) + t * FF + d];
}

// ---------------- fused 3-layer wavefront (R16 core + L0-gate pairing) --------
// 125 CTAs x 256 threads, persistent, 702 steps.
//   cta  0..24 : L0, 16 units (64 cols), k=400(+3 aux). 2 col-halves x 4 k-slices.
//   cta 25..74 : L1,  8 units (32 cols), k=800. 8 k-slices(100).
//   cta 75..124: L2,  8 units (32 cols), k=800. 8 k-slices(100).
// Dataflow barrier: L0 polls flags[0,25); L1 [0,75); L2 [25,125).
// L0 gate: each thread = SAME unit, 2 adjacent batch-pairs -> LDS.128 reduce
// loads, shared unit params, fused STG.128 h-store.
// Aux x-rows: one row each on slices 0/1/2 (balanced 101/101/101/100).
#define WSM_BYTES 102400
#define RED_BYTES 65536
#define WAVE_SMEM (WSM_BYTES + RED_BYTES + 768)

template<int NC>   // 64 (L0) or 32 (L1/2)
__device__ __forceinline__ void accum100(ull (&acc)[8][4],
                                         const float* __restrict__ wrow0,
                                         const float* __restrict__ hsrc,
                                         int pg)
{
    const char* hp = (const char*)hsrc + pg * 32;   // this thread's 4 pairs
    ulonglong2 hb[2][4][2];                          // [buf][row][half]
#pragma unroll
    for (int j = 0; j < 4; j++) {
        hb[0][j][0] = *(const ulonglong2*)(hp + j * 256);
        hb[0][j][1] = *(const ulonglong2*)(hp + j * 256 + 16);
    }
    const float* wrow = wrow0;
#pragma unroll 2
    for (int rc = 0; rc < 100; rc += 4) {
        int cur = (rc >> 2) & 1;
        if (rc < 96) {
            int nxt = cur ^ 1;
#pragma unroll
            for (int j = 0; j < 4; j++) {
                hb[nxt][j][0] = *(const ulonglong2*)(hp + (rc + 4 + j) * 256);
                hb[nxt][j][1] = *(const ulonglong2*)(hp + (rc + 4 + j) * 256 + 16);
            }
        }
#pragma unroll
        for (int j = 0; j < 4; j++) {
            float4 wa = *(const float4*)(wrow);
            float4 wb = *(const float4*)(wrow + 4);
            ull w0 = dup2(wa.x), w1 = dup2(wa.y), w2 = dup2(wa.z), w3 = dup2(wa.w);
            ull w4 = dup2(wb.x), w5 = dup2(wb.y), w6 = dup2(wb.z), w7 = dup2(wb.w);
            ulonglong2 hA = hb[cur][j][0];
            ulonglong2 hB = hb[cur][j][1];
            ffma2(acc[0][0], hA.x, w0); ffma2(acc[0][1], hA.y, w0);
            ffma2(acc[0][2], hB.x, w0); ffma2(acc[0][3], hB.y, w0);
            ffma2(acc[1][0], hA.x, w1); ffma2(acc[1][1], hA.y, w1);
            ffma2(acc[1][2], hB.x, w1); ffma2(acc[1][3], hB.y, w1);
            ffma2(acc[2][0], hA.x, w2); ffma2(acc[2][1], hA.y, w2);
            ffma2(acc[2][2], hB.x, w2); ffma2(acc[2][3], hB.y, w2);
            ffma2(acc[3][0], hA.x, w3); ffma2(acc[3][1], hA.y, w3);
            ffma2(acc[3][2], hB.x, w3); ffma2(acc[3][3], hB.y, w3);
            ffma2(acc[4][0], hA.x, w4); ffma2(acc[4][1], hA.y, w4);
            ffma2(acc[4][2], hB.x, w4); ffma2(acc[4][3], hB.y, w4);
            ffma2(acc[5][0], hA.x, w5); ffma2(acc[5][1], hA.y, w5);
            ffma2(acc[5][2], hB.x, w5); ffma2(acc[5][3], hB.y, w5);
            ffma2(acc[6][0], hA.x, w6); ffma2(acc[6][1], hA.y, w6);
            ffma2(acc[6][2], hB.x, w6); ffma2(acc[6][3], hB.y, w6);
            ffma2(acc[7][0], hA.x, w7); ffma2(acc[7][1], hA.y, w7);
            ffma2(acc[7][2], hB.x, w7); ffma2(acc[7][3], hB.y, w7);
            wrow += NC;
        }
    }
}

// single aux row (input x), same h-row layout (256 B stride)
__device__ __forceinline__ void accum1(ull (&acc)[8][4],
                                       const float* __restrict__ wrowaux,  // + col offset, row j
                                       const float* __restrict__ xrow,     // g_xaux + t*192 + j*64
                                       int pg)
{
    const char* hp = (const char*)xrow + pg * 32;
    ulonglong2 hA = *(const ulonglong2*)hp;
    ulonglong2 hB = *(const ulonglong2*)(hp + 16);
    float4 wa = *(const float4*)(wrowaux);
    float4 wb = *(const float4*)(wrowaux + 4);
    ull w0 = dup2(wa.x), w1 = dup2(wa.y), w2 = dup2(wa.z), w3 = dup2(wa.w);
    ull w4 = dup2(wb.x), w5 = dup2(wb.y), w6 = dup2(wb.z), w7 = dup2(wb.w);
    ffma2(acc[0][0], hA.x, w0); ffma2(acc[0][1], hA.y, w0);
    ffma2(acc[0][2], hB.x, w0); ffma2(acc[0][3], hB.y, w0);
    ffma2(acc[1][0], hA.x, w1); ffma2(acc[1][1], hA.y, w1);
    ffma2(acc[1][2], hB.x, w1); ffma2(acc[1][3], hB.y, w1);
    ffma2(acc[2][0], hA.x, w2); ffma2(acc[2][1], hA.y, w2);
    ffma2(acc[2][2], hB.x, w2); ffma2(acc[2][3], hB.y, w2);
    ffma2(acc[3][0], hA.x, w3); ffma2(acc[3][1], hA.y, w3);
    ffma2(acc[3][2], hB.x, w3); ffma2(acc[3][3], hB.y, w3);
    ffma2(acc[4][0], hA.x, w4); ffma2(acc[4][1], hA.y, w4);
    ffma2(acc[4][2], hB.x, w4); ffma2(acc[4][3], hB.y, w4);
    ffma2(acc[5][0], hA.x, w5); ffma2(acc[5][1], hA.y, w5);
    ffma2(acc[5][2], hB.x, w5); ffma2(acc[5][3], hB.y, w5);
    ffma2(acc[6][0], hA.x, w6); ffma2(acc[6][1], hA.y, w6);
    ffma2(acc[6][2], hB.x, w6); ffma2(acc[6][3], hB.y, w6);
    ffma2(acc[7][0], hA.x, w7); ffma2(acc[7][1], hA.y, w7);
    ffma2(acc[7][2], hB.x, w7); ffma2(acc[7][3], hB.y, w7);
}

// LSTM cell, one unit, two batches; z packed f32x2 per gate; returns packed h.
__device__ __forceinline__ ull cell2v(const ull z[4], float& c0, float& c1,
                                      float piv, float pfv, float pov)
{
    float zi0 = f2lo(z[0]), zi1 = f2hi(z[0]);
    float zf0 = f2lo(z[1]), zf1 = f2hi(z[1]);
    float zg0 = f2lo(z[2]), zg1 = f2hi(z[2]);
    float zo0 = f2lo(z[3]), zo1 = f2hi(z[3]);

    float i0 = sigm(zi0 + piv * c0);
    float f0 = sigm(zf0 + pfv * c0);
    float cn0 = f0 * c0 + i0 * tanh_fast(zg0);
    float o0 = sigm(zo0 + pov * cn0);
    float h0 = o0 * tanh_fast(cn0);
    c0 = cn0;

    float i1 = sigm(zi1 + piv * c1);
    float f1 = sigm(zf1 + pfv * c1);
    float cn1 = f1 * c1 + i1 * tanh_fast(zg1);
    float o1 = sigm(zo1 + pov * cn1);
    float h1 = o1 * tanh_fast(cn1);
    c1 = cn1;

    return pack2(h0, h1);
}

__global__ void __launch_bounds__(256, 1) wave_kernel(const float* __restrict__ Wx0,
                                                      const float* __restrict__ Wx1,
                                                      const float* __restrict__ Wx2,
                                                      const float* __restrict__ Wh,
                                                      const float* __restrict__ bb,
                                                      const float* __restrict__ pi,
                                                      const float* __restrict__ pf,
                                                      const float* __restrict__ po)
{
    extern __shared__ char smraw[];
    float* wsm  = (float*)smraw;                           // [krows][ncols] fp32
    ull*   red  = (ull*)(smraw + WSM_BYTES);               // [nslice][ncolsTot][32 pairs]
    float* waux = (float*)(smraw + WSM_BYTES + RED_BYTES); // [3][64] L0 x-row weights

    const int tid  = threadIdx.x;
    const int cta  = blockIdx.x;
    const int wid  = tid >> 5;
    const int lane = tid & 31;
    const int cg   = lane & 3;     // col-group (8 cols)
    const int pg   = lane >> 2;    // pair-group (4 pairs)

    int jtype, ubase, nu;
    if (cta < 25)      { jtype = 0; ubase = cta * 16;        nu = 16; }
    else if (cta < 75) { jtype = 1; ubase = (cta - 25) * 8;  nu = 8;  }
    else               { jtype = 2; ubase = (cta - 75) * 8;  nu = 8;  }
    const int ncols  = nu * 4;                  // 64 or 32
    const int nslice = (jtype == 0) ? 4 : 8;

    // dataflow-barrier poll range
    int plo, phi;
    if (jtype == 0)      { plo = 0;  phi = 25;  }
    else if (jtype == 1) { plo = 0;  phi = 75;  }
    else                 { plo = 25; phi = 125; }

    const float* Wh0 = Wh;
    const float* Wh1 = Wh + (size_t)UU * GG;
    const float* Wh2 = Wh + (size_t)2 * UU * GG;

    // ---- weight fill: 25600 fp32 (+ L0 aux rows) ----
    for (int idx = tid; idx < 25600; idx += 256) {
        int k, c;
        if (jtype == 0) { k = idx >> 6; c = idx & 63; }
        else            { k = idx >> 5; c = idx & 31; }
        int ul = c >> 2, g = c & 3, u = ubase + ul;
        float v;
        if (jtype == 0)      v = Wh0[(size_t)k * GG + g * UU + u];
        else if (jtype == 1) v = (k < 400) ? Wx1[(size_t)k * GG + g * UU + u]
                                           : Wh1[(size_t)(k - 400) * GG + g * UU + u];
        else                 v = (k < 400) ? Wx2[(size_t)k * GG + g * UU + u]
                                           : Wh2[(size_t)(k - 400) * GG + g * UU + u];
        wsm[idx] = v;
    }
    if (jtype == 0) {
        for (int idx = tid; idx < 3 * 64; idx += 256) {
            int j = idx >> 6, c = idx & 63;
            int ul = c >> 2, g = c & 3, u = ubase + ul;
            waux[idx] = Wx0[(size_t)j * GG + g * UU + u];
        }
    }

    // ---- gate-cell constants ----
    // L0: thread = SAME unit (tid>>4), 2 adjacent batch-pairs (cpb, cpb+1).
    // L1/2: thread = one (unit, pair) cell.
    int cu, cpb;
    if (jtype == 0) { cu = ubase + (tid >> 4); cpb = (tid & 15) * 2; }
    else            { cu = ubase + (tid >> 5); cpb = tid & 31;       }
    float piv = pi[jtype * UU + cu];
    float pfv = pf[jtype * UU + cu];
    float pov = po[jtype * UU + cu];
    ull bz[4];
#pragma unroll
    for (int g = 0; g < 4; g++) bz[g] = dup2(bb[jtype * GG + g * UU + cu]);
    float cst[4] = {0.f, 0.f, 0.f, 0.f};   // c-state: up to 2 cells x 2 batches

    // ---- compute-warp mapping ----
    int sl, chalf;
    if (jtype == 0) { chalf = wid >> 2; sl = wid & 3; }   // 2 halves x 4 slices
    else            { chalf = 0;        sl = wid;     }   // 8 slices
    const int mycol0 = chalf * 32 + cg * 8;
    const float* wrow0 = wsm + (size_t)(sl * 100) * ncols + mycol0;
    const float* wauxp = waux + mycol0;

    const unsigned base = g_flags[cta];
    __syncthreads();

    for (int s = 0; s < NSTEPS; s++) {
        const int t = s - jtype;
        const bool act = (t >= 0) && (t < TT);

        ull acc[8][4];
#pragma unroll
        for (int c = 0; c < 8; c++)
#pragma unroll
            for (int p = 0; p < 4; p++) acc[c][p] = 0ull;

        if (act) {
            // folded L0 input projection: one aux row each on slices 0/1/2,
            // front-loaded so the LDG latency overlaps the main k-loop
            if (jtype == 0 && sl < 3)
                accum1(acc, wauxp + sl * 64,
                       g_xaux + (size_t)t * (3 * BB) + sl * BB, pg);

            const float* hsrc = nullptr;
            if (jtype == 0) {
                if (t > 0) hsrc = g_h0 + ((size_t)(t - 1) * UU + sl * 100) * BB;
            } else {
                if (sl < 4) {
                    hsrc = ((jtype == 1) ? g_h0 : g_h1) + ((size_t)t * UU + sl * 100) * BB;
                } else if (t > 0) {
                    hsrc = ((jtype == 1) ? g_h1 : g_h2) + ((size_t)(t - 1) * UU + (sl - 4) * 100) * BB;
                }
            }
            if (hsrc) {
                if (jtype == 0) accum100<64>(acc, wrow0, hsrc, pg);
                else            accum100<32>(acc, wrow0, hsrc, pg);
            }

            // partial-sum store: red[sl][col][pair], ull elements
            const int ncolsTot = (jtype == 0) ? 64 : 32;
            ull* rp = red + ((size_t)sl * ncolsTot + mycol0) * 32 + pg * 4;
#pragma unroll
            for (int c = 0; c < 8; c++) {
                ulonglong2 s0; s0.x = acc[c][0]; s0.y = acc[c][1];
                ulonglong2 s1; s1.x = acc[c][2]; s1.y = acc[c][3];
                *(ulonglong2*)(rp + (size_t)c * 32)     = s0;
                *(ulonglong2*)(rp + (size_t)c * 32 + 2) = s1;
            }
        }
        __syncthreads();

        // gate phase
        if (act) {
            const int ul4 = (cu - ubase) << 2;
            if (jtype == 0) {
                // paired cells (same unit, pairs cpb & cpb+1): LDS.128 reduce
                ull zA[4], zB[4];
#pragma unroll
                for (int g = 0; g < 4; g++) {
                    ull sa = bz[g], sb = bz[g];
                    const ull* rp2 = red + (size_t)(ul4 + g) * 32 + cpb;
#pragma unroll
                    for (int s2 = 0; s2 < 4; s2++) {
                        ulonglong2 v = *(const ulonglong2*)(rp2 + (size_t)s2 * 64 * 32);
                        sa = add2(sa, v.x);
                        sb = add2(sb, v.y);
                    }
                    zA[g] = sa; zB[g] = sb;
                }
                ull hA = cell2v(zA, cst[0], cst[1], piv, pfv, pov);
                ull hB = cell2v(zB, cst[2], cst[3], piv, pfv, pov);
                ulonglong2 hh; hh.x = hA; hh.y = hB;
                *(ulonglong2*)(g_h0 + ((size_t)t * UU + cu) * BB + 2 * cpb) = hh;
            } else {
                ull z[4];
#pragma unroll
                for (int g = 0; g < 4; g++) {
                    ull zz = bz[g];
                    const ull* rp2 = red + (size_t)(ul4 + g) * 32 + cpb;
                    for (int s2 = 0; s2 < 8; s2++)
                        zz = add2(zz, rp2[(size_t)s2 * 32 * 32]);
                    z[g] = zz;
                }
                ull hv = cell2v(z, cst[0], cst[1], piv, pfv, pov);
                float* hout = ((jtype == 1) ? g_h1 : g_h2)
                              + ((size_t)t * UU + cu) * BB + 2 * cpb;
                *(ull*)hout = hv;
            }
        }
        __syncthreads();   // all CTA stores done before release

        if (s < NSTEPS - 1) {
            unsigned tgt = base + (unsigned)s + 1u;
            if (tid == 0) st_rel(&g_flags[cta], tgt);
            if (tid < 32) {
                for (;;) {
                    bool ok = true;
                    for (int i = plo + lane; i < phi; i += 32)
                        if (ld_acq(&g_flags[i]) < tgt) ok = false;
                    if (__all_sync(0xffffffffu, ok)) break;
                    __nanosleep(8);
                }
            }
            __syncthreads();
        }
    }
}

// ---------------- final projection ------------------------------------------
__global__ void final_kernel(const float* __restrict__ Wd,
                             const float* __restrict__ bd,
                             float* __restrict__ out)
{
    int t = blockIdx.x;
    int tid = threadIdx.x;  // 192
    __shared__ float wds[UU * FF];
    for (int i = tid; i < UU * FF; i += 192) wds[i] = Wd[i];
    __syncthreads();
    int b = tid / FF, f = tid % FF;
    const float* h = g_h2 + (size_t)t * UU * BB;
    float acc = bd[f];
#pragma unroll 4
    for (int u = 0; u < UU; u++)
        acc += h[(size_t)u * BB + b] * wds[u * FF + f];
    out[(size_t)b * (TT * FF) + t * FF + f] = acc;
}

// ---------------- launch -----------------------------------------------------
extern "C" void kernel_launch(void* const* d_in, const int* in_sizes, int n_in,
                              void* d_out, int out_size)
{
    (void)in_sizes; (void)n_in; (void)out_size;
    const float* x   = (const float*)d_in[0];
    const float* Wx0 = (const float*)d_in[1];
    const float* Wx1 = (const float*)d_in[2];
    const float* Wx2 = (const float*)d_in[3];
    const float* Wh  = (const float*)d_in[4];
    const float* bb  = (const float*)d_in[5];
    const float* pi  = (const float*)d_in[6];
    const float* pf  = (const float*)d_in[7];
    const float* po  = (const float*)d_in[8];
    const float* Wd  = (const float*)d_in[9];
    const float* bd  = (const float*)d_in[10];
    float* out = (float*)d_out;

    cudaFuncSetAttribute(wave_kernel, cudaFuncAttributeMaxDynamicSharedMemorySize, WAVE_SMEM);

    // transpose x to [t][d][b] (input projection folded into the wave)
    xt_kernel<<<TT, 192>>>(x);
    // fused 3-layer wavefront with layer-local dataflow barriers
    wave_kernel<<<NCTA_W, 256, WAVE_SMEM>>>(Wx0, Wx1, Wx2, Wh, bb, pi, pf, po);
    // output projection
    final_kernel<<<TT, 192>>>(Wd, bd, out);
}